// round 8
// baseline (speedup 1.0000x reference)
#include <cuda_runtime.h>
#include <cuda_fp16.h>
#include <cstdint>

#define DIM 256
#define NQ  8192
#define NE  8192
#define NW  64               // 64 int32 words per row (256 int8)
#define ZQ_ELEMS (NQ * DIM)
#define NTILE 64             // code tiles of 128
#define BNPW 132             // padded Bs row stride (ints)
#define CAND_CAP 64

#define A_SZ   (64 * 64 * 4)                 // 16384
#define B_SZ   (NW * BNPW * 4)               // 33792
#define RED_SZ (64 * 32 * 4)                 // 8192
#define SMEM_SC (A_SZ + 2 * B_SZ + RED_SZ)   // 92160

// ---------------- device scratch (device-side references only) ----------------
__device__ float g_znorm[NQ * DIM];
__device__ float g_znorm2[NQ];
__device__ float g_zinv[NQ];
__device__ float g_zdel[NQ];
__device__ int   g_qz[NQ * NW];
__device__ float g_enorm[NE * DIM];
__device__ float g_enorm2[NE];
__device__ float g_einv[NE];
__device__ float g_edel[NE];
__device__ int   g_qe[NE * NW];
__device__ __half g_keys[(size_t)NQ * NE];   // 134 MB approx keys
__device__ float g_rowbest[NQ];
__device__ float g_demax[1];
__device__ int   g_cand[NQ * CAND_CAP];
__device__ int   g_cnt[NQ];
__device__ int   g_idx[NQ];
__device__ float g_partial[1024];

// ---------------- L2 normalize + int8 quantize ----------------
__global__ void norm_quant(const float* __restrict__ in, int rows, int is_code) {
    int row  = (blockIdx.x * blockDim.x + threadIdx.x) >> 5;
    int lane = threadIdx.x & 31;
    if (row >= rows) return;
    float* __restrict__ outv = is_code ? g_enorm : g_znorm;
    const float4* src = (const float4*)(in + (size_t)row * DIM);
    float4 v0 = src[lane];
    float4 v1 = src[lane + 32];
    float s = v0.x*v0.x + v0.y*v0.y + v0.z*v0.z + v0.w*v0.w
            + v1.x*v1.x + v1.y*v1.y + v1.z*v1.z + v1.w*v1.w;
    #pragma unroll
    for (int off = 16; off; off >>= 1) s += __shfl_xor_sync(0xffffffffu, s, off);
    float inv = 1.0f / fmaxf(sqrtf(s), 1e-12f);
    v0.x *= inv; v0.y *= inv; v0.z *= inv; v0.w *= inv;
    v1.x *= inv; v1.y *= inv; v1.z *= inv; v1.w *= inv;
    float4* dst = (float4*)(outv + (size_t)row * DIM);
    dst[lane]      = v0;
    dst[lane + 32] = v1;

    float vals[8] = {v0.x, v0.y, v0.z, v0.w, v1.x, v1.y, v1.z, v1.w};
    float s2 = 0.f;
    #pragma unroll
    for (int j = 0; j < 8; j++) s2 += vals[j] * vals[j];
    #pragma unroll
    for (int off = 16; off; off >>= 1) s2 += __shfl_xor_sync(0xffffffffu, s2, off);

    float mx = 0.f;
    #pragma unroll
    for (int j = 0; j < 8; j++) mx = fmaxf(mx, fabsf(vals[j]));
    #pragma unroll
    for (int off = 16; off; off >>= 1) mx = fmaxf(mx, __shfl_xor_sync(0xffffffffu, mx, off));
    float sc    = 127.0f / mx;
    float scinv = mx / 127.0f;

    int h[8];
    float dsum = 0.f;
    #pragma unroll
    for (int j = 0; j < 8; j++) {
        h[j] = (int)rintf(vals[j] * sc);
        float e = vals[j] - (float)h[j] * scinv;
        dsum += e * e;
    }
    #pragma unroll
    for (int off = 16; off; off >>= 1) dsum += __shfl_xor_sync(0xffffffffu, dsum, off);

    int w0 = (h[0] & 0xFF) | ((h[1] & 0xFF) << 8) | ((h[2] & 0xFF) << 16) | (h[3] << 24);
    int w1 = (h[4] & 0xFF) | ((h[5] & 0xFF) << 8) | ((h[6] & 0xFF) << 16) | (h[7] << 24);
    int* qp = is_code ? g_qe : g_qz;
    qp[(size_t)row * NW + lane]      = w0;
    qp[(size_t)row * NW + 32 + lane] = w1;
    if (lane == 0) {
        if (is_code) { g_enorm2[row] = s2; g_einv[row] = scinv; g_edel[row] = sqrtf(dsum); }
        else         { g_znorm2[row] = s2; g_zinv[row] = scinv; g_zdel[row] = sqrtf(dsum); }
    }
}

__global__ void demax_reduce() {
    __shared__ float sh[256];
    int tid = threadIdx.x;
    float m = 0.f;
    for (int i = tid; i < NE; i += 256) m = fmaxf(m, g_edel[i]);
    sh[tid] = m;
    __syncthreads();
    for (int off = 128; off; off >>= 1) {
        if (tid < off) sh[tid] = fmaxf(sh[tid], sh[tid + off]);
        __syncthreads();
    }
    if (tid == 0) g_demax[0] = sh[0];
}

// ---------------- int8 dp4a screen: fp16 keys + per-row best ----------------
__global__ __launch_bounds__(256, 1)
void screen() {
    extern __shared__ char smem[];
    int*   As  = (int*)smem;                       // [NW][64] transposed
    int*   Bs  = (int*)(smem + A_SZ);              // [2][NW][BNPW] transposed
    float* red = (float*)(smem + A_SZ + 2 * B_SZ); // [64][32]

    const int tid = threadIdx.x;
    const int tx  = tid & 31;
    const int ty  = tid >> 5;
    const int qbase = blockIdx.x * 64;

    {
        int row = tid >> 2, p = tid & 3;
        #pragma unroll
        for (int j = 0; j < 4; j++) {
            int w = p * 16 + j * 4;
            int4 v = *(const int4*)&g_qz[(size_t)(qbase + row) * NW + w];
            As[(w + 0) * 64 + row] = v.x;
            As[(w + 1) * 64 + row] = v.y;
            As[(w + 2) * 64 + row] = v.z;
            As[(w + 3) * 64 + row] = v.w;
        }
    }

    float z2s[8], qiv[8];
    #pragma unroll
    for (int i = 0; i < 8; i++) {
        int r = qbase + ty * 8 + i;
        z2s[i] = g_znorm2[r];
        qiv[i] = g_zinv[r];
    }
    float bestv[8];
    #pragma unroll
    for (int i = 0; i < 8; i++) bestv[i] = 3.4e38f;

    const int c  = tid >> 1;
    const int hf = tid & 1;
    int4 br[8];

    #pragma unroll
    for (int j = 0; j < 8; j++)
        br[j] = *(const int4*)&g_qe[(size_t)c * NW + hf * 32 + j * 4];
    #pragma unroll
    for (int j = 0; j < 8; j++) {
        int w = hf * 32 + j * 4;
        Bs[(w + 0) * BNPW + c] = br[j].x;
        Bs[(w + 1) * BNPW + c] = br[j].y;
        Bs[(w + 2) * BNPW + c] = br[j].z;
        Bs[(w + 3) * BNPW + c] = br[j].w;
    }
    __syncthreads();

    int acc[8][4];

    #pragma unroll 1
    for (int t = 0; t < NTILE; t++) {
        const int buf = t & 1;
        #pragma unroll
        for (int i = 0; i < 8; i++) {
            acc[i][0] = 0; acc[i][1] = 0; acc[i][2] = 0; acc[i][3] = 0;
        }
        if (t + 1 < NTILE) {
            #pragma unroll
            for (int j = 0; j < 8; j++)
                br[j] = *(const int4*)&g_qe[(size_t)((t + 1) * 128 + c) * NW + hf * 32 + j * 4];
        }

        const int* B = Bs + buf * (NW * BNPW);
        #pragma unroll 8
        for (int kw = 0; kw < NW; kw++) {
            int4 a0 = *(const int4*)&As[kw * 64 + ty * 8];
            int4 a1 = *(const int4*)&As[kw * 64 + ty * 8 + 4];
            int4 b  = *(const int4*)&B[kw * BNPW + tx * 4];
            acc[0][0] = __dp4a(a0.x, b.x, acc[0][0]); acc[0][1] = __dp4a(a0.x, b.y, acc[0][1]);
            acc[0][2] = __dp4a(a0.x, b.z, acc[0][2]); acc[0][3] = __dp4a(a0.x, b.w, acc[0][3]);
            acc[1][0] = __dp4a(a0.y, b.x, acc[1][0]); acc[1][1] = __dp4a(a0.y, b.y, acc[1][1]);
            acc[1][2] = __dp4a(a0.y, b.z, acc[1][2]); acc[1][3] = __dp4a(a0.y, b.w, acc[1][3]);
            acc[2][0] = __dp4a(a0.z, b.x, acc[2][0]); acc[2][1] = __dp4a(a0.z, b.y, acc[2][1]);
            acc[2][2] = __dp4a(a0.z, b.z, acc[2][2]); acc[2][3] = __dp4a(a0.z, b.w, acc[2][3]);
            acc[3][0] = __dp4a(a0.w, b.x, acc[3][0]); acc[3][1] = __dp4a(a0.w, b.y, acc[3][1]);
            acc[3][2] = __dp4a(a0.w, b.z, acc[3][2]); acc[3][3] = __dp4a(a0.w, b.w, acc[3][3]);
            acc[4][0] = __dp4a(a1.x, b.x, acc[4][0]); acc[4][1] = __dp4a(a1.x, b.y, acc[4][1]);
            acc[4][2] = __dp4a(a1.x, b.z, acc[4][2]); acc[4][3] = __dp4a(a1.x, b.w, acc[4][3]);
            acc[5][0] = __dp4a(a1.y, b.x, acc[5][0]); acc[5][1] = __dp4a(a1.y, b.y, acc[5][1]);
            acc[5][2] = __dp4a(a1.y, b.z, acc[5][2]); acc[5][3] = __dp4a(a1.y, b.w, acc[5][3]);
            acc[6][0] = __dp4a(a1.z, b.x, acc[6][0]); acc[6][1] = __dp4a(a1.z, b.y, acc[6][1]);
            acc[6][2] = __dp4a(a1.z, b.z, acc[6][2]); acc[6][3] = __dp4a(a1.z, b.w, acc[6][3]);
            acc[7][0] = __dp4a(a1.w, b.x, acc[7][0]); acc[7][1] = __dp4a(a1.w, b.y, acc[7][1]);
            acc[7][2] = __dp4a(a1.w, b.z, acc[7][2]); acc[7][3] = __dp4a(a1.w, b.w, acc[7][3]);
        }

        if (t + 1 < NTILE) {
            int* Bn = Bs + ((t + 1) & 1) * (NW * BNPW);
            #pragma unroll
            for (int j = 0; j < 8; j++) {
                int w = hf * 32 + j * 4;
                Bn[(w + 0) * BNPW + c] = br[j].x;
                Bn[(w + 1) * BNPW + c] = br[j].y;
                Bn[(w + 2) * BNPW + c] = br[j].z;
                Bn[(w + 3) * BNPW + c] = br[j].w;
            }
        }
        __syncthreads();

        int colb = t * 128 + tx * 4;
        float4 e2  = *(const float4*)&g_enorm2[colb];
        float4 civ = *(const float4*)&g_einv[colb];
        #pragma unroll
        for (int i = 0; i < 8; i++) {
            float sc = qiv[i];
            float k0 = z2s[i] + e2.x - 2.0f * ((float)acc[i][0] * (sc * civ.x));
            float k1 = z2s[i] + e2.y - 2.0f * ((float)acc[i][1] * (sc * civ.y));
            float k2 = z2s[i] + e2.z - 2.0f * ((float)acc[i][2] * (sc * civ.z));
            float k3 = z2s[i] + e2.w - 2.0f * ((float)acc[i][3] * (sc * civ.w));
            bestv[i] = fminf(bestv[i], fminf(fminf(k0, k1), fminf(k2, k3)));
            __half2 p01 = __floats2half2_rn(k0, k1);
            __half2 p23 = __floats2half2_rn(k2, k3);
            uint2 pk;
            pk.x = *(uint32_t*)&p01;
            pk.y = *(uint32_t*)&p23;
            *(uint2*)&g_keys[(size_t)(qbase + ty * 8 + i) * NE + colb] = pk;
        }
    }

    #pragma unroll
    for (int i = 0; i < 8; i++) red[(ty * 8 + i) * 32 + tx] = bestv[i];
    __syncthreads();
    if (tid < 64) {
        float bv = 3.4e38f;
        #pragma unroll 8
        for (int t2 = 0; t2 < 32; t2++) bv = fminf(bv, red[tid * 32 + t2]);
        g_rowbest[qbase + tid] = bv;
    }
}

// ---------------- candidate collection (provable margin) ----------------
__global__ void collect() {
    __shared__ int scand[CAND_CAP];
    __shared__ int scnt;
    int row = blockIdx.x;
    int tid = threadIdx.x;
    if (tid == 0) scnt = 0;
    __syncthreads();

    float dq = g_zdel[row];
    float D  = g_demax[0];
    float B  = dq + D + 3.0f * dq * D;
    float thresh = g_rowbest[row] + 4.0f * B + 0.01f;

    const uint4* kp = (const uint4*)&g_keys[(size_t)row * NE];
    for (int it = 0; it < NE / (128 * 8); it++) {
        uint4 v = kp[tid + it * 128];
        int cbase = (tid + it * 128) * 8;
        uint32_t ws[4] = {v.x, v.y, v.z, v.w};
        #pragma unroll
        for (int wI = 0; wI < 4; wI++) {
            __half2 h2 = *(__half2*)&ws[wI];
            float f0 = __low2float(h2), f1 = __high2float(h2);
            if (f0 <= thresh) { int s = atomicAdd(&scnt, 1); if (s < CAND_CAP) scand[s] = cbase + wI * 2; }
            if (f1 <= thresh) { int s = atomicAdd(&scnt, 1); if (s < CAND_CAP) scand[s] = cbase + wI * 2 + 1; }
        }
    }
    __syncthreads();
    int n = scnt;
    if (tid < CAND_CAP && tid < n) g_cand[row * CAND_CAP + tid] = scand[tid];
    if (tid == 0) g_cnt[row] = n;
}

// ---------------- exact rescoring ----------------
__global__ void rescore() {
    __shared__ unsigned long long wmin[8];
    int row = blockIdx.x;
    int tid = threadIdx.x;
    int lane = tid & 31;
    int w = tid >> 5;
    int cnt = g_cnt[row];
    float z2 = g_znorm2[row];
    const float* zr = &g_znorm[(size_t)row * DIM];

    unsigned long long lmin = 0xFFFFFFFFFFFFFFFFull;

    if (cnt > 0 && cnt <= CAND_CAP) {
        const float4* zv = (const float4*)zr;
        float4 b0 = zv[lane], b1 = zv[lane + 32];
        for (int i = w; i < cnt; i += 8) {
            int code = g_cand[row * CAND_CAP + i];
            const float4* ev = (const float4*)&g_enorm[(size_t)code * DIM];
            float4 a0 = ev[lane], a1 = ev[lane + 32];
            float d = a0.x*b0.x + a0.y*b0.y + a0.z*b0.z + a0.w*b0.w
                    + a1.x*b1.x + a1.y*b1.y + a1.z*b1.z + a1.w*b1.w;
            #pragma unroll
            for (int off = 16; off; off >>= 1) d += __shfl_xor_sync(0xffffffffu, d, off);
            float key = z2 + g_enorm2[code] - 2.0f * d;
            unsigned long long p = ((unsigned long long)__float_as_uint(key) << 32) | (unsigned)code;
            lmin = min(lmin, p);
        }
    } else {
        for (int n = tid; n < NE; n += 256) {
            const float* er = &g_enorm[(size_t)n * DIM];
            float dot = 0.f;
            #pragma unroll 8
            for (int d2 = 0; d2 < DIM; d2++) dot = fmaf(zr[d2], er[d2], dot);
            float key = z2 + g_enorm2[n] - 2.0f * dot;
            unsigned long long p = ((unsigned long long)__float_as_uint(key) << 32) | (unsigned)n;
            lmin = min(lmin, p);
        }
    }
    #pragma unroll
    for (int off = 16; off; off >>= 1) {
        unsigned long long o = __shfl_xor_sync(0xffffffffu, lmin, off);
        lmin = min(lmin, o);
    }
    if (lane == 0) wmin[w] = lmin;
    __syncthreads();
    if (tid == 0) {
        unsigned long long m = wmin[0];
        #pragma unroll
        for (int i = 1; i < 8; i++) m = min(m, wmin[i]);
        g_idx[row] = (int)(m & 0xFFFFFFFFull);
    }
}

// ---------------- gather z_q, loss partials, index output ----------------
__global__ void gather_loss(float* __restrict__ zq_out, float* __restrict__ idxf_out,
                            int write_zq) {
    __shared__ float wsum[8];
    int tid = threadIdx.x;
    int lane = tid & 31;
    int w = tid >> 5;
    int row = blockIdx.x * 8 + w;

    int e = g_idx[row] & (NE - 1);
    const float4* ev = (const float4*)(g_enorm + (size_t)e * DIM);
    const float4* zv = (const float4*)(g_znorm + (size_t)row * DIM);
    float4 a0 = ev[lane], a1 = ev[lane + 32];
    float4 b0 = zv[lane], b1 = zv[lane + 32];

    if (write_zq) {
        float4* o = (float4*)(zq_out + (size_t)row * DIM);
        o[lane]      = a0;
        o[lane + 32] = a1;
    }
    float dx, s = 0.f;
    dx = a0.x - b0.x; s += dx * dx;  dx = a0.y - b0.y; s += dx * dx;
    dx = a0.z - b0.z; s += dx * dx;  dx = a0.w - b0.w; s += dx * dx;
    dx = a1.x - b1.x; s += dx * dx;  dx = a1.y - b1.y; s += dx * dx;
    dx = a1.z - b1.z; s += dx * dx;  dx = a1.w - b1.w; s += dx * dx;
    #pragma unroll
    for (int off = 16; off; off >>= 1) s += __shfl_xor_sync(0xffffffffu, s, off);
    if (lane == 0) {
        wsum[w] = s;
        if (idxf_out) idxf_out[row] = (float)e;
    }
    __syncthreads();
    if (tid == 0) {
        float t = 0.f;
        #pragma unroll
        for (int i = 0; i < 8; i++) t += wsum[i];
        g_partial[blockIdx.x] = t;
    }
}

__global__ void finalize_loss(float* __restrict__ loss_out) {
    __shared__ float sh[256];
    int tid = threadIdx.x;
    float s = 0.f;
    for (int i = tid; i < 1024; i += 256) s += g_partial[i];
    sh[tid] = s;
    __syncthreads();
    for (int off = 128; off; off >>= 1) {
        if (tid < off) sh[tid] += sh[tid + off];
        __syncthreads();
    }
    if (tid == 0 && loss_out) loss_out[0] = 1.25f * sh[0] / (float)ZQ_ELEMS;
}

// ---------------- launch (no __device__ symbols below!) ----------------
extern "C" void kernel_launch(void* const* d_in, const int* in_sizes, int n_in,
                              void* d_out, int out_size) {
    const float* z  = (const float*)d_in[0];
    const float* ew = (const float*)d_in[1];
    float* out = (float*)d_out;

    int   write_zq = 0;
    float* lossp = nullptr;
    float* idxf  = nullptr;
    if (out_size >= ZQ_ELEMS) {
        write_zq = 1;
        long R = (long)out_size - (long)ZQ_ELEMS;
        if (R >= (long)NQ + 1)      { lossp = out + ZQ_ELEMS; idxf = out + ZQ_ELEMS + 1; }
        else if (R == (long)NQ)     { idxf = out + ZQ_ELEMS; }
        else if (R >= 1)            { lossp = out + ZQ_ELEMS; }
    } else if (out_size == NQ) {
        idxf = out;
    } else if (out_size == 1) {
        lossp = out;
    }

    static int smem_set = 0;
    if (!smem_set) {
        cudaFuncSetAttribute(screen, cudaFuncAttributeMaxDynamicSharedMemorySize, SMEM_SC);
        smem_set = 1;
    }

    norm_quant<<<NE / 8, 256>>>(ew, NE, 1);
    norm_quant<<<NQ / 8, 256>>>(z, NQ, 0);
    demax_reduce<<<1, 256>>>();
    screen<<<NQ / 64, 256, SMEM_SC>>>();
    collect<<<NQ, 128>>>();
    rescore<<<NQ, 256>>>();
    gather_loss<<<NQ / 8, 256>>>(out, idxf, write_zq);
    finalize_loss<<<1, 256>>>(lossp);
}